// round 5
// baseline (speedup 1.0000x reference)
#include <cuda_runtime.h>
#include <math.h>

#define NND 50000
#define NE  800000
#define HIDN 128
#define NODE_IN 32
#define EDGE_IN 16
#define CIN 272        // 2*HID + EDGE_IN
#define UIN 256        // 2*HID
#define HPAD 132
#define XPAD 36
#define TN 32

typedef unsigned long long ull;

// ---------------- persistent scratch ----------------
__device__ float g_h[NND * HIDN];
__device__ float g_aggr[NND * HIDN];
__device__ float g_invd[NND];
__device__ int   g_cnt[NND];
__device__ int   g_is64;

// ---------------- packed f32x2 helpers ----------------
__device__ __forceinline__ ull fma2(ull a, ull b, ull c) {
    ull d;
    asm("fma.rn.f32x2 %0, %1, %2, %3;" : "=l"(d) : "l"(a), "l"(b), "l"(c));
    return d;
}
__device__ __forceinline__ ull dup2(float a) {
    ull d; unsigned r = __float_as_uint(a);
    asm("mov.b64 %0, {%1, %1};" : "=l"(d) : "r"(r));
    return d;
}
__device__ __forceinline__ float2 unpack2(ull v) {
    unsigned lo, hi;
    asm("mov.b64 {%0, %1}, %2;" : "=r"(lo), "=r"(hi) : "l"(v));
    return make_float2(__uint_as_float(lo), __uint_as_float(hi));
}

// ---------------- async copy helpers ----------------
__device__ __forceinline__ void cp16(float* dst_smem, const float* src) {
    unsigned d = (unsigned)__cvta_generic_to_shared(dst_smem);
    asm volatile("cp.async.ca.shared.global [%0], [%1], 16;" :: "r"(d), "l"(src));
}
__device__ __forceinline__ void cp_commit() {
    asm volatile("cp.async.commit_group;");
}
template<int N> __device__ __forceinline__ void cp_wait() {
    asm volatile("cp.async.wait_group %0;" :: "n"(N));
}
// stage one 16x128 fp32 W chunk (2048 floats) with 128 threads (16 floats each)
__device__ __forceinline__ void stage_w128(float* dst, const float* src, int tid) {
    int o = tid * 16;
    cp16(dst + o,      src + o);
    cp16(dst + o + 4,  src + o + 4);
    cp16(dst + o + 8,  src + o + 8);
    cp16(dst + o + 12, src + o + 12);
}

// vector reduction into global (fp32 x4)
__device__ __forceinline__ void red4(float* addr, float4 v) {
    asm volatile("red.global.add.v4.f32 [%0], {%1, %2, %3, %4};"
                 :: "l"(addr), "f"(v.x), "f"(v.y), "f"(v.z), "f"(v.w) : "memory");
}

// ---------------- edge index (int32/int64 runtime-detected) ----------------
__device__ __forceinline__ void load_edge(const void* ei, int e, int& s, int& t) {
    if (g_is64) {
        const long long* p = (const long long*)ei;
        s = (int)p[e];
        t = (int)p[NE + e];
    } else {
        const int* p = (const int*)ei;
        s = p[e];
        t = p[NE + e];
    }
}

// ---------------- setup kernels ----------------
__global__ void init_kernel() {
    int i = blockIdx.x * blockDim.x + threadIdx.x;
    int stride = gridDim.x * blockDim.x;
    if (i == 0) g_is64 = 1;
    for (int j = i; j < NND; j += stride) g_cnt[j] = 0;
    for (int j = i; j < NND * HIDN; j += stride) g_aggr[j] = 0.f;
}
__global__ void detect_kernel(const unsigned* w) {
    int stride = gridDim.x * blockDim.x;
    bool nz = false;
    for (int i = blockIdx.x * blockDim.x + threadIdx.x; i < NE; i += stride)
        nz |= (w[2 * i + 1] != 0u);
    if (nz) g_is64 = 0;
}
__global__ void count_kernel(const void* ei) {
    int stride = gridDim.x * blockDim.x;
    for (int e = blockIdx.x * blockDim.x + threadIdx.x; e < NE; e += stride) {
        int s, t; load_edge(ei, e, s, t);
        atomicAdd(&g_cnt[t], 1);
    }
}
__global__ void inv_kernel() {
    int n = blockIdx.x * blockDim.x + threadIdx.x;
    if (n < NND) g_invd[n] = 1.f / fmaxf((float)g_cnt[n], 1.f);
}

// ============================================================================
// Fused edge MLP + scatter.  64 edges/block, 128 threads.
// Register tile: 8 edges x 8 channels/thread.  W staged in smem (cp.async x2),
// single-sync software pipeline:  wait; sync; stage(c+1); compute(c)
// SMEM: s_in[64][272] | wbuf[2][2048] | s_t[64]  => 86272B  (2 blocks/SM)
// ============================================================================
#define EDGE_SMEM (64*272*4 + 2*2048*4 + 64*4)

__global__ void __launch_bounds__(128) edge_kernel2(
        const void* ei, const float* ea,
        const float* W1, const float* b1,
        const float* W2, const float* b2) {
    extern __shared__ float sm[];
    float* s_in  = sm;                       // [64][272]
    float* wb    = sm + 64 * 272;            // [2][2048]
    int*   s_t   = (int*)(sm + 64 * 272 + 2 * 2048);
    float* s_hid = sm;                       // alias [64][128]

    int tid = threadIdx.x, lane = tid & 31, warp = tid >> 5;
    int eb = blockIdx.x * 64;

    // prefetch W1 chunk 0 (overlaps gather)
    stage_w128(wb, W1, tid); cp_commit();

    // gather [x_i | x_j | edge_attr]
    for (int j = warp; j < 64; j += 4) {
        int e = eb + j, s, t;
        load_edge(ei, e, s, t);
        if (lane == 0) s_t[j] = t;
        *(float4*)&s_in[j * 272 + 4 * lane]       = *(const float4*)&g_h[t * HIDN + 4 * lane];
        *(float4*)&s_in[j * 272 + 128 + 4 * lane] = *(const float4*)&g_h[s * HIDN + 4 * lane];
        if (lane < 4)
            *(float4*)&s_in[j * 272 + 256 + 4 * lane] =
                *(const float4*)&ea[(size_t)e * EDGE_IN + 4 * lane];
    }

    int cg = tid & 15, egp = tid >> 4;     // 16 channel groups x 8 edge groups
    int c0 = 8 * cg, e0 = 8 * egp;

    // ---------------- GEMM1: [64,272] @ [272,128], relu ----------------
    ull acc[8][4];
    {
        ulonglong2 bA = *(const ulonglong2*)(b1 + c0);
        ulonglong2 bB = *(const ulonglong2*)(b1 + c0 + 4);
#pragma unroll
        for (int i = 0; i < 8; i++) {
            acc[i][0] = bA.x; acc[i][1] = bA.y; acc[i][2] = bB.x; acc[i][3] = bB.y;
        }
    }
    for (int c = 0; c < 17; c++) {
        cp_wait<0>();
        __syncthreads();                 // chunk c ready; prev chunk reads done
        if (c < 16) { stage_w128(wb + ((c + 1) & 1) * 2048, W1 + (c + 1) * 2048, tid); cp_commit(); }
        const float* w = wb + (c & 1) * 2048;
        int kb = c * 16;
#pragma unroll
        for (int k4 = 0; k4 < 16; k4 += 4) {
            float4 av[8];
#pragma unroll
            for (int i = 0; i < 8; i++)
                av[i] = *(const float4*)&s_in[(e0 + i) * 272 + kb + k4];
#pragma unroll
            for (int kk = 0; kk < 4; kk++) {
                const float* wr = w + (k4 + kk) * 128 + c0;
                ulonglong2 w0 = *(const ulonglong2*)(wr);
                ulonglong2 w1 = *(const ulonglong2*)(wr + 4);
#pragma unroll
                for (int i = 0; i < 8; i++) {
                    float a = (kk == 0) ? av[i].x : (kk == 1) ? av[i].y :
                              (kk == 2) ? av[i].z : av[i].w;
                    ull ad = dup2(a);
                    acc[i][0] = fma2(ad, w0.x, acc[i][0]);
                    acc[i][1] = fma2(ad, w0.y, acc[i][1]);
                    acc[i][2] = fma2(ad, w1.x, acc[i][2]);
                    acc[i][3] = fma2(ad, w1.y, acc[i][3]);
                }
            }
        }
    }
    __syncthreads();                     // last chunk reads done before s_hid alias write

    // prefetch W2 chunk 0 into buf0 (safe: all W1 reads complete)
    stage_w128(wb, W2, tid); cp_commit();

    // relu -> s_hid (aliases s_in)
#pragma unroll
    for (int i = 0; i < 8; i++) {
        float2 p0 = unpack2(acc[i][0]), p1 = unpack2(acc[i][1]);
        float2 p2 = unpack2(acc[i][2]), p3 = unpack2(acc[i][3]);
        *(float4*)&s_hid[(e0 + i) * 128 + c0] =
            make_float4(fmaxf(p0.x, 0.f), fmaxf(p0.y, 0.f), fmaxf(p1.x, 0.f), fmaxf(p1.y, 0.f));
        *(float4*)&s_hid[(e0 + i) * 128 + c0 + 4] =
            make_float4(fmaxf(p2.x, 0.f), fmaxf(p2.y, 0.f), fmaxf(p3.x, 0.f), fmaxf(p3.y, 0.f));
    }

    // ---------------- GEMM2: [64,128] @ [128,128] ----------------
    ull acc2[8][4];
    {
        ulonglong2 bA = *(const ulonglong2*)(b2 + c0);
        ulonglong2 bB = *(const ulonglong2*)(b2 + c0 + 4);
#pragma unroll
        for (int i = 0; i < 8; i++) {
            acc2[i][0] = bA.x; acc2[i][1] = bA.y; acc2[i][2] = bB.x; acc2[i][3] = bB.y;
        }
    }
    for (int c = 0; c < 8; c++) {
        cp_wait<0>();
        __syncthreads();                 // also covers s_hid writes on c==0
        if (c < 7) { stage_w128(wb + ((c + 1) & 1) * 2048, W2 + (c + 1) * 2048, tid); cp_commit(); }
        const float* w = wb + (c & 1) * 2048;
        int kb = c * 16;
#pragma unroll
        for (int k4 = 0; k4 < 16; k4 += 4) {
            float4 av[8];
#pragma unroll
            for (int i = 0; i < 8; i++)
                av[i] = *(const float4*)&s_hid[(e0 + i) * 128 + kb + k4];
#pragma unroll
            for (int kk = 0; kk < 4; kk++) {
                const float* wr = w + (k4 + kk) * 128 + c0;
                ulonglong2 w0 = *(const ulonglong2*)(wr);
                ulonglong2 w1 = *(const ulonglong2*)(wr + 4);
#pragma unroll
                for (int i = 0; i < 8; i++) {
                    float a = (kk == 0) ? av[i].x : (kk == 1) ? av[i].y :
                              (kk == 2) ? av[i].z : av[i].w;
                    ull ad = dup2(a);
                    acc2[i][0] = fma2(ad, w0.x, acc2[i][0]);
                    acc2[i][1] = fma2(ad, w0.y, acc2[i][1]);
                    acc2[i][2] = fma2(ad, w1.x, acc2[i][2]);
                    acc2[i][3] = fma2(ad, w1.y, acc2[i][3]);
                }
            }
        }
    }

    // scatter (mean aggregation numerator)
#pragma unroll
    for (int i = 0; i < 8; i++) {
        int t = s_t[e0 + i];
        float2 p0 = unpack2(acc2[i][0]), p1 = unpack2(acc2[i][1]);
        float2 p2 = unpack2(acc2[i][2]), p3 = unpack2(acc2[i][3]);
        red4(&g_aggr[t * HIDN + c0],     make_float4(p0.x, p0.y, p1.x, p1.y));
        red4(&g_aggr[t * HIDN + c0 + 4], make_float4(p2.x, p2.y, p3.x, p3.y));
    }
}

// ============================================================================
// Node update: h = LN(h + MLP([h, aggr/deg])).  64 nodes/block, 128 threads,
// 8 nodes x 8 channels/thread, single-sync pipeline.
// SMEM: s_in[64][256] | wbuf[2][2048]  => 81920B
// ============================================================================
#define UPD_SMEM (64*256*4 + 2*2048*4)

__global__ void __launch_bounds__(128) update_kernel2(
        const float* W1, const float* b1,
        const float* W2, const float* b2,
        const float* gw, const float* gb) {
    extern __shared__ float sm[];
    float* s_in  = sm;                 // [64][256]
    float* wb    = sm + 64 * 256;      // [2][2048]
    float* s_hid = sm;                 // alias [64][128]

    int tid = threadIdx.x, lane = tid & 31, warp = tid >> 5;
    int nb = blockIdx.x * 64;

    stage_w128(wb, W1, tid); cp_commit();

    // gather [h | aggr/deg]
    for (int j = warp; j < 64; j += 4) {
        int n = nb + j;
        if (n < NND) {
            float inv = g_invd[n];
            float4 hv = *(const float4*)&g_h[n * HIDN + 4 * lane];
            float4 av = *(const float4*)&g_aggr[n * HIDN + 4 * lane];
            av.x *= inv; av.y *= inv; av.z *= inv; av.w *= inv;
            *(float4*)&s_in[j * 256 + 4 * lane] = hv;
            *(float4*)&s_in[j * 256 + 128 + 4 * lane] = av;
        } else {
            *(float4*)&s_in[j * 256 + 4 * lane] = make_float4(0.f, 0.f, 0.f, 0.f);
            *(float4*)&s_in[j * 256 + 128 + 4 * lane] = make_float4(0.f, 0.f, 0.f, 0.f);
        }
    }

    int cg = tid & 15, egp = tid >> 4;
    int c0 = 8 * cg, e0 = 8 * egp;

    // ---------------- GEMM1: [64,256] @ [256,128], relu ----------------
    ull acc[8][4];
    {
        ulonglong2 bA = *(const ulonglong2*)(b1 + c0);
        ulonglong2 bB = *(const ulonglong2*)(b1 + c0 + 4);
#pragma unroll
        for (int i = 0; i < 8; i++) {
            acc[i][0] = bA.x; acc[i][1] = bA.y; acc[i][2] = bB.x; acc[i][3] = bB.y;
        }
    }
    for (int c = 0; c < 16; c++) {
        cp_wait<0>();
        __syncthreads();
        if (c < 15) { stage_w128(wb + ((c + 1) & 1) * 2048, W1 + (c + 1) * 2048, tid); cp_commit(); }
        const float* w = wb + (c & 1) * 2048;
        int kb = c * 16;
#pragma unroll
        for (int k4 = 0; k4 < 16; k4 += 4) {
            float4 av[8];
#pragma unroll
            for (int i = 0; i < 8; i++)
                av[i] = *(const float4*)&s_in[(e0 + i) * 256 + kb + k4];
#pragma unroll
            for (int kk = 0; kk < 4; kk++) {
                const float* wr = w + (k4 + kk) * 128 + c0;
                ulonglong2 w0 = *(const ulonglong2*)(wr);
                ulonglong2 w1 = *(const ulonglong2*)(wr + 4);
#pragma unroll
                for (int i = 0; i < 8; i++) {
                    float a = (kk == 0) ? av[i].x : (kk == 1) ? av[i].y :
                              (kk == 2) ? av[i].z : av[i].w;
                    ull ad = dup2(a);
                    acc[i][0] = fma2(ad, w0.x, acc[i][0]);
                    acc[i][1] = fma2(ad, w0.y, acc[i][1]);
                    acc[i][2] = fma2(ad, w1.x, acc[i][2]);
                    acc[i][3] = fma2(ad, w1.y, acc[i][3]);
                }
            }
        }
    }
    __syncthreads();

    stage_w128(wb, W2, tid); cp_commit();

#pragma unroll
    for (int i = 0; i < 8; i++) {
        float2 p0 = unpack2(acc[i][0]), p1 = unpack2(acc[i][1]);
        float2 p2 = unpack2(acc[i][2]), p3 = unpack2(acc[i][3]);
        *(float4*)&s_hid[(e0 + i) * 128 + c0] =
            make_float4(fmaxf(p0.x, 0.f), fmaxf(p0.y, 0.f), fmaxf(p1.x, 0.f), fmaxf(p1.y, 0.f));
        *(float4*)&s_hid[(e0 + i) * 128 + c0 + 4] =
            make_float4(fmaxf(p2.x, 0.f), fmaxf(p2.y, 0.f), fmaxf(p3.x, 0.f), fmaxf(p3.y, 0.f));
    }

    // ---------------- GEMM2: [64,128] @ [128,128] ----------------
    ull acc2[8][4];
    {
        ulonglong2 bA = *(const ulonglong2*)(b2 + c0);
        ulonglong2 bB = *(const ulonglong2*)(b2 + c0 + 4);
#pragma unroll
        for (int i = 0; i < 8; i++) {
            acc2[i][0] = bA.x; acc2[i][1] = bA.y; acc2[i][2] = bB.x; acc2[i][3] = bB.y;
        }
    }
    for (int c = 0; c < 8; c++) {
        cp_wait<0>();
        __syncthreads();
        if (c < 7) { stage_w128(wb + ((c + 1) & 1) * 2048, W2 + (c + 1) * 2048, tid); cp_commit(); }
        const float* w = wb + (c & 1) * 2048;
        int kb = c * 16;
#pragma unroll
        for (int k4 = 0; k4 < 16; k4 += 4) {
            float4 av[8];
#pragma unroll
            for (int i = 0; i < 8; i++)
                av[i] = *(const float4*)&s_hid[(e0 + i) * 128 + kb + k4];
#pragma unroll
            for (int kk = 0; kk < 4; kk++) {
                const float* wr = w + (k4 + kk) * 128 + c0;
                ulonglong2 w0 = *(const ulonglong2*)(wr);
                ulonglong2 w1 = *(const ulonglong2*)(wr + 4);
#pragma unroll
                for (int i = 0; i < 8; i++) {
                    float a = (kk == 0) ? av[i].x : (kk == 1) ? av[i].y :
                              (kk == 2) ? av[i].z : av[i].w;
                    ull ad = dup2(a);
                    acc2[i][0] = fma2(ad, w0.x, acc2[i][0]);
                    acc2[i][1] = fma2(ad, w0.y, acc2[i][1]);
                    acc2[i][2] = fma2(ad, w1.x, acc2[i][2]);
                    acc2[i][3] = fma2(ad, w1.y, acc2[i][3]);
                }
            }
        }
    }

    // residual + LayerNorm + store (16 threads of a half-warp hold one node row)
    float4 g0 = *(const float4*)&gw[c0], g1 = *(const float4*)&gw[c0 + 4];
    float4 bb0 = *(const float4*)&gb[c0], bb1 = *(const float4*)&gb[c0 + 4];
#pragma unroll
    for (int i = 0; i < 8; i++) {
        int n = nb + e0 + i;
        float2 p0 = unpack2(acc2[i][0]), p1 = unpack2(acc2[i][1]);
        float2 p2 = unpack2(acc2[i][2]), p3 = unpack2(acc2[i][3]);
        float4 h0 = make_float4(0.f, 0.f, 0.f, 0.f), h1 = h0;
        if (n < NND) {
            h0 = *(const float4*)&g_h[n * HIDN + c0];
            h1 = *(const float4*)&g_h[n * HIDN + c0 + 4];
        }
        float o[8];
        o[0] = p0.x + h0.x; o[1] = p0.y + h0.y; o[2] = p1.x + h0.z; o[3] = p1.y + h0.w;
        o[4] = p2.x + h1.x; o[5] = p2.y + h1.y; o[6] = p3.x + h1.z; o[7] = p3.y + h1.w;
        float s = 0.f, q = 0.f;
#pragma unroll
        for (int k = 0; k < 8; k++) { s += o[k]; q += o[k] * o[k]; }
#pragma unroll
        for (int off = 1; off < 16; off <<= 1) {
            s += __shfl_xor_sync(0xffffffffu, s, off);
            q += __shfl_xor_sync(0xffffffffu, q, off);
        }
        float mean = s * (1.f / 128.f);
        float var  = q * (1.f / 128.f) - mean * mean;
        float rs   = rsqrtf(var + 1e-5f);
        if (n < NND) {
            float4 r0, r1;
            r0.x = (o[0] - mean) * rs * g0.x + bb0.x;
            r0.y = (o[1] - mean) * rs * g0.y + bb0.y;
            r0.z = (o[2] - mean) * rs * g0.z + bb0.z;
            r0.w = (o[3] - mean) * rs * g0.w + bb0.w;
            r1.x = (o[4] - mean) * rs * g1.x + bb1.x;
            r1.y = (o[5] - mean) * rs * g1.y + bb1.y;
            r1.z = (o[6] - mean) * rs * g1.z + bb1.z;
            r1.w = (o[7] - mean) * rs * g1.w + bb1.w;
            *(float4*)&g_h[n * HIDN + c0]     = r0;
            *(float4*)&g_h[n * HIDN + c0 + 4] = r1;
            *(float4*)&g_aggr[n * HIDN + c0]     = make_float4(0.f, 0.f, 0.f, 0.f);
            *(float4*)&g_aggr[n * HIDN + c0 + 4] = make_float4(0.f, 0.f, 0.f, 0.f);
        }
    }
}

// ---------------- layernorm + store helper (legacy node kernels) ----------
__device__ __forceinline__ void ln_store(float (*s_out)[HPAD], int nb,
                                         const float* gw, const float* gb) {
    int tid = threadIdx.x;
    int nn = tid >> 3;
    int p  = tid & 7;
    int n  = nb + nn;
    float vals[16];
    float sum = 0.f, sq = 0.f;
#pragma unroll
    for (int i = 0; i < 4; i++) {
        float4 t4 = *(float4*)&s_out[nn][16 * p + 4 * i];
        vals[4*i+0] = t4.x; vals[4*i+1] = t4.y; vals[4*i+2] = t4.z; vals[4*i+3] = t4.w;
        sum += t4.x + t4.y + t4.z + t4.w;
        sq  += t4.x*t4.x + t4.y*t4.y + t4.z*t4.z + t4.w*t4.w;
    }
#pragma unroll
    for (int off = 4; off; off >>= 1) {
        sum += __shfl_xor_sync(0xffffffffu, sum, off);
        sq  += __shfl_xor_sync(0xffffffffu, sq,  off);
    }
    float mean = sum * (1.f / 128.f);
    float var  = sq * (1.f / 128.f) - mean * mean;
    float rs   = rsqrtf(var + 1e-5f);
    if (n < NND) {
#pragma unroll
        for (int i = 0; i < 4; i++) {
            int c = 16 * p + 4 * i;
            float4 o;
            o.x = (vals[4*i+0] - mean) * rs * gw[c + 0] + gb[c + 0];
            o.y = (vals[4*i+1] - mean) * rs * gw[c + 1] + gb[c + 1];
            o.z = (vals[4*i+2] - mean) * rs * gw[c + 2] + gb[c + 2];
            o.w = (vals[4*i+3] - mean) * rs * gw[c + 3] + gb[c + 3];
            *(float4*)&g_h[n * HIDN + c] = o;
        }
    }
}

// ---------------- encoder: h = LN(relu(x @ W + b)) ----------------
__global__ __launch_bounds__(256) void encoder_kernel(const float* x, const float* W,
                                                      const float* b, const float* gw,
                                                      const float* gb) {
    __shared__ float s_in[TN][XPAD];
    __shared__ float s_out[TN][HPAD];
    int tid = threadIdx.x, lane = tid & 31, w = tid >> 5;
    int nb = blockIdx.x * TN;
    for (int j = w; j < TN; j += 8) {
        int n = nb + j;
        if (lane < 8) {
            float4 v = make_float4(0.f, 0.f, 0.f, 0.f);
            if (n < NND) v = *(const float4*)&x[n * NODE_IN + 4 * lane];
            *(float4*)&s_in[j][4 * lane] = v;
        }
    }
    __syncthreads();
    int cg = tid & 31, c0 = 4 * cg, eg = tid >> 5, e0 = 4 * eg;
    ull acc[4][2];
    {
        ull b01 = *(const ull*)(b + c0), b23 = *(const ull*)(b + c0 + 2);
#pragma unroll
        for (int i = 0; i < 4; i++) { acc[i][0] = b01; acc[i][1] = b23; }
    }
#pragma unroll
    for (int k = 0; k < NODE_IN; k++) {
        ulonglong2 wv = *(const ulonglong2*)(W + k * HIDN + c0);
#pragma unroll
        for (int i = 0; i < 4; i++) {
            ull a = dup2(s_in[e0 + i][k]);
            acc[i][0] = fma2(a, wv.x, acc[i][0]);
            acc[i][1] = fma2(a, wv.y, acc[i][1]);
        }
    }
#pragma unroll
    for (int i = 0; i < 4; i++) {
        float2 v0 = unpack2(acc[i][0]), v1 = unpack2(acc[i][1]);
        s_out[e0 + i][c0 + 0] = fmaxf(v0.x, 0.f);
        s_out[e0 + i][c0 + 1] = fmaxf(v0.y, 0.f);
        s_out[e0 + i][c0 + 2] = fmaxf(v1.x, 0.f);
        s_out[e0 + i][c0 + 3] = fmaxf(v1.y, 0.f);
    }
    __syncthreads();
    ln_store(s_out, nb, gw, gb);
}

// ---------------- head: out = h @ head_W + head_b ----------------
__global__ __launch_bounds__(256) void head_kernel(const float* W, const float* b,
                                                   float* out) {
    __shared__ float s_in[TN][HPAD];
    int tid = threadIdx.x, lane = tid & 31, w = tid >> 5;
    int nb = blockIdx.x * TN;
    for (int j = w; j < TN; j += 8) {
        int n = nb + j;
        float4 v = make_float4(0.f, 0.f, 0.f, 0.f);
        if (n < NND) v = *(const float4*)&g_h[n * HIDN + 4 * lane];
        *(float4*)&s_in[j][4 * lane] = v;
    }
    __syncthreads();
    int cg = tid & 31, c0 = 4 * cg, eg = tid >> 5, e0 = 4 * eg;
    ull acc[4][2];
    {
        ull b01 = *(const ull*)(b + c0), b23 = *(const ull*)(b + c0 + 2);
#pragma unroll
        for (int i = 0; i < 4; i++) { acc[i][0] = b01; acc[i][1] = b23; }
    }
#pragma unroll 4
    for (int k = 0; k < HIDN; k++) {
        ulonglong2 wv = *(const ulonglong2*)(W + k * HIDN + c0);
#pragma unroll
        for (int i = 0; i < 4; i++) {
            ull a = dup2(s_in[e0 + i][k]);
            acc[i][0] = fma2(a, wv.x, acc[i][0]);
            acc[i][1] = fma2(a, wv.y, acc[i][1]);
        }
    }
#pragma unroll
    for (int i = 0; i < 4; i++) {
        int n = nb + e0 + i;
        if (n < NND) {
            float2 v0 = unpack2(acc[i][0]), v1 = unpack2(acc[i][1]);
            *(float2*)&out[n * HIDN + c0 + 0] = v0;
            *(float2*)&out[n * HIDN + c0 + 2] = v1;
        }
    }
}

// ---------------- launch ----------------
extern "C" void kernel_launch(void* const* d_in, const int* in_sizes, int n_in,
                              void* d_out, int out_size) {
    const float* x      = (const float*)d_in[0];
    const void*  ei     = d_in[1];
    const float* ea     = (const float*)d_in[2];
    const float* enc_W  = (const float*)d_in[3];
    const float* enc_b  = (const float*)d_in[4];
    const float* enc_g  = (const float*)d_in[5];
    const float* enc_be = (const float*)d_in[6];
    const float* msg_W1 = (const float*)d_in[7];
    const float* msg_b1 = (const float*)d_in[8];
    const float* msg_W2 = (const float*)d_in[9];
    const float* msg_b2 = (const float*)d_in[10];
    const float* upd_W1 = (const float*)d_in[11];
    const float* upd_b1 = (const float*)d_in[12];
    const float* upd_W2 = (const float*)d_in[13];
    const float* upd_b2 = (const float*)d_in[14];
    const float* ln_g   = (const float*)d_in[15];
    const float* ln_be  = (const float*)d_in[16];
    const float* head_W = (const float*)d_in[17];
    const float* head_b = (const float*)d_in[18];
    float* out = (float*)d_out;

    cudaFuncSetAttribute(edge_kernel2, cudaFuncAttributeMaxDynamicSharedMemorySize, EDGE_SMEM);
    cudaFuncSetAttribute(update_kernel2, cudaFuncAttributeMaxDynamicSharedMemorySize, UPD_SMEM);

    init_kernel<<<256, 256>>>();
    detect_kernel<<<256, 256>>>((const unsigned*)ei);
    count_kernel<<<512, 256>>>(ei);
    inv_kernel<<<(NND + 255) / 256, 256>>>();

    int nblk32 = (NND + TN - 1) / TN;
    int nblk64 = (NND + 63) / 64;
    encoder_kernel<<<nblk32, 256>>>(x, enc_W, enc_b, enc_g, enc_be);

    for (int l = 0; l < 2; l++) {
        edge_kernel2<<<NE / 64, 128, EDGE_SMEM>>>(ei, ea,
                                      msg_W1 + l * CIN * HIDN, msg_b1 + l * HIDN,
                                      msg_W2 + l * HIDN * HIDN, msg_b2 + l * HIDN);
        update_kernel2<<<nblk64, 128, UPD_SMEM>>>(upd_W1 + l * UIN * HIDN, upd_b1 + l * HIDN,
                                     upd_W2 + l * HIDN * HIDN, upd_b2 + l * HIDN,
                                     ln_g + l * HIDN, ln_be + l * HIDN);
    }
    head_kernel<<<nblk32, 256>>>(head_W, head_b, out);
}

// round 7
// speedup vs baseline: 1.4983x; 1.4983x over previous
#include <cuda_runtime.h>
#include <math.h>
#include <stdint.h>

#define NND 50000
#define NE  800000
#define HIDN 128
#define NODE_IN 32
#define EDGE_IN 16
#define CIN 272
#define UIN 256
#define HPAD 132
#define XPAD 36
#define TN 32
#define K8_1 34
#define K8_2 16
#define W1F (K8_1*1024)
#define W2F (K8_2*1024)
#define ASTR 276
#define HSTR 132

typedef unsigned long long ull;

__device__ float g_h[NND * HIDN];
__device__ float g_aggr[NND * HIDN];
__device__ float g_invd[NND];
__device__ int   g_cnt[NND];
__device__ int   g_is64;
__device__ __align__(16) float g_w1h[2 * W1F];
__device__ __align__(16) float g_w1l[2 * W1F];
__device__ __align__(16) float g_w2h[2 * W2F];
__device__ __align__(16) float g_w2l[2 * W2F];

// ---------- tf32 round-to-nearest ----------
__device__ __forceinline__ float tf32r(float x) {
    unsigned u; asm("cvt.rna.tf32.f32 %0, %1;" : "=r"(u) : "f"(x));
    return __uint_as_float(u);
}
// ---------- f32x2 (node kernels) ----------
__device__ __forceinline__ ull fma2(ull a, ull b, ull c) {
    ull d; asm("fma.rn.f32x2 %0, %1, %2, %3;" : "=l"(d) : "l"(a), "l"(b), "l"(c)); return d;
}
__device__ __forceinline__ ull dup2(float a) {
    ull d; unsigned r = __float_as_uint(a);
    asm("mov.b64 %0, {%1, %1};" : "=l"(d) : "r"(r)); return d;
}
__device__ __forceinline__ float2 unpack2(ull v) {
    unsigned lo, hi; asm("mov.b64 {%0, %1}, %2;" : "=r"(lo), "=r"(hi) : "l"(v));
    return make_float2(__uint_as_float(lo), __uint_as_float(hi));
}
// ---------- cp.async ----------
__device__ __forceinline__ void cp16(float* dst, const float* src) {
    unsigned d = (unsigned)__cvta_generic_to_shared(dst);
    asm volatile("cp.async.ca.shared.global [%0], [%1], 16;" :: "r"(d), "l"(src));
}
__device__ __forceinline__ void cp_commit() { asm volatile("cp.async.commit_group;"); }
template<int N> __device__ __forceinline__ void cp_wait() {
    asm volatile("cp.async.wait_group %0;" :: "n"(N));
}
__device__ __forceinline__ void stage_w128(float* dst, const float* src, int tid) {
    int o = tid * 16;
    cp16(dst + o, src + o); cp16(dst + o + 4, src + o + 4);
    cp16(dst + o + 8, src + o + 8); cp16(dst + o + 12, src + o + 12);
}
// ---------- global reductions ----------
__device__ __forceinline__ void red2(float* a, float2 v) {
    asm volatile("red.global.add.v2.f32 [%0], {%1, %2};"
                 :: "l"(a), "f"(v.x), "f"(v.y) : "memory");
}
// ---------- tf32 mma ----------
__device__ __forceinline__ void mma8(float* c, const unsigned* a, float2 b) {
    asm volatile("mma.sync.aligned.m16n8k8.row.col.f32.tf32.tf32.f32 "
        "{%0,%1,%2,%3}, {%4,%5,%6,%7}, {%8,%9}, {%0,%1,%2,%3};"
        : "+f"(c[0]), "+f"(c[1]), "+f"(c[2]), "+f"(c[3])
        : "r"(a[0]), "r"(a[1]), "r"(a[2]), "r"(a[3]),
          "r"(__float_as_uint(b.x)), "r"(__float_as_uint(b.y)));
}
// ---------- edge index ----------
__device__ __forceinline__ void load_edge(const void* ei, int e, int& s, int& t) {
    if (g_is64) { const long long* p = (const long long*)ei; s = (int)p[e]; t = (int)p[NE + e]; }
    else        { const int* p = (const int*)ei;             s = p[e];      t = p[NE + e]; }
}
// ---------- setup ----------
__global__ void init_kernel() {
    int i = blockIdx.x * blockDim.x + threadIdx.x, st = gridDim.x * blockDim.x;
    if (i == 0) g_is64 = 1;
    for (int j = i; j < NND; j += st) g_cnt[j] = 0;
    for (int j = i; j < NND * HIDN; j += st) g_aggr[j] = 0.f;
}
__global__ void detect_kernel(const unsigned* w) {
    int st = gridDim.x * blockDim.x; bool nz = false;
    for (int i = blockIdx.x * blockDim.x + threadIdx.x; i < NE; i += st) nz |= (w[2 * i + 1] != 0u);
    if (nz) g_is64 = 0;
}
__global__ void count_kernel(const void* ei) {
    int st = gridDim.x * blockDim.x;
    for (int e = blockIdx.x * blockDim.x + threadIdx.x; e < NE; e += st) {
        int s, t; load_edge(ei, e, s, t); atomicAdd(&g_cnt[t], 1);
    }
}
__global__ void inv_kernel() {
    int n = blockIdx.x * blockDim.x + threadIdx.x;
    if (n < NND) g_invd[n] = 1.f / fmaxf((float)g_cnt[n], 1.f);
}
// ---------- weight packing: B-fragment order, tf32 hi/lo ----------
// layout per layer: [k8][nt(16)][lane(32)][2]; b0=W[k8*8+tig][nt*8+gid], b1=W[k+4][n]
__global__ void pack_w1f(const float* W1) {
    int i = blockIdx.x * blockDim.x + threadIdx.x;
    if (i >= 2 * K8_1 * 512) return;
    int lane = i & 31, r = i >> 5;
    int nt = r & 15; r >>= 4;
    int k8 = r % K8_1, l = r / K8_1;
    int gid = lane >> 2, tig = lane & 3;
    int n = nt * 8 + gid;
    int k0 = k8 * 8 + tig, k1 = k0 + 4;
    float v0 = W1[(l * CIN + k0) * 128 + n];
    float v1 = W1[(l * CIN + k1) * 128 + n];
    float h0 = tf32r(v0), h1 = tf32r(v1);
    int off = l * W1F + ((k8 * 16 + nt) * 32 + lane) * 2;
    g_w1h[off] = h0; g_w1h[off + 1] = h1;
    g_w1l[off] = tf32r(v0 - h0); g_w1l[off + 1] = tf32r(v1 - h1);
}
__global__ void pack_w2f(const float* W2) {
    int i = blockIdx.x * blockDim.x + threadIdx.x;
    if (i >= 2 * K8_2 * 512) return;
    int lane = i & 31, r = i >> 5;
    int nt = r & 15; r >>= 4;
    int k8 = r % K8_2, l = r / K8_2;
    int gid = lane >> 2, tig = lane & 3;
    int n = nt * 8 + gid;
    int k0 = k8 * 8 + tig, k1 = k0 + 4;
    float v0 = W2[(l * 128 + k0) * 128 + n];
    float v1 = W2[(l * 128 + k1) * 128 + n];
    float h0 = tf32r(v0), h1 = tf32r(v1);
    int off = l * W2F + ((k8 * 16 + nt) * 32 + lane) * 2;
    g_w2h[off] = h0; g_w2h[off + 1] = h1;
    g_w2l[off] = tf32r(v0 - h0); g_w2l[off + 1] = tf32r(v1 - h1);
}
// ============================================================================
// tf32 mma.sync edge kernel: 128 edges/CTA, 256 threads (8 warps).
// warp = (wg = edge-group of 32, nh = col half of 64). 2 m-tiles x 8 n-tiles.
// SMEM: s_t[128]@0 | sb1@512 | sb2@1024 | s_in[128][276]@1536 | wb[2][2048]
// ============================================================================
#define EK_SMEM (1536 + 128*ASTR*4 + 2*2048*4)

__global__ void __launch_bounds__(256) edge_mma(const void* ei, const float* ea,
        const float* b1v, const float* b2v, int layer) {
    extern __shared__ char smc[];
    int*   s_t  = (int*)smc;
    float* sb1  = (float*)(smc + 512);
    float* sb2  = (float*)(smc + 1024);
    float* s_in = (float*)(smc + 1536);
    float* s_hid = s_in;                       // stride HSTR, alias
    float* wb   = (float*)(smc + 1536 + 128 * ASTR * 4);   // [2][2048]
    const float* w1h = g_w1h + layer * W1F;
    const float* w1l = g_w1l + layer * W1F;
    const float* w2h = g_w2h + layer * W2F;
    const float* w2l = g_w2l + layer * W2F;

    int tid = threadIdx.x, lane = tid & 31, warp = tid >> 5;
    int wg = warp >> 1, nh = warp & 1;
    int gid = lane >> 2, tig = lane & 3;
    int eb = blockIdx.x * 128;

    if (tid < 128) { sb1[tid] = b1v[tid]; sb2[tid] = b2v[tid]; }
    // stage W1 chunk 0
    cp16(wb + tid * 4, w1h + tid * 4);
    cp16(wb + 1024 + tid * 4, w1l + tid * 4);
    cp_commit();
    // gather [x_i | x_j | ea], tf32-rounded
    for (int j = warp; j < 128; j += 8) {
        int e = eb + j, s, t; load_edge(ei, e, s, t);
        if (lane == 0) s_t[j] = t;
        float* d = s_in + j * ASTR;
        float4 a = *(const float4*)&g_h[(size_t)t * HIDN + 4 * lane];
        d[4 * lane + 0] = tf32r(a.x); d[4 * lane + 1] = tf32r(a.y);
        d[4 * lane + 2] = tf32r(a.z); d[4 * lane + 3] = tf32r(a.w);
        float4 b = *(const float4*)&g_h[(size_t)s * HIDN + 4 * lane];
        d[128 + 4 * lane + 0] = tf32r(b.x); d[128 + 4 * lane + 1] = tf32r(b.y);
        d[128 + 4 * lane + 2] = tf32r(b.z); d[128 + 4 * lane + 3] = tf32r(b.w);
        if (lane < 4) {
            float4 c = *(const float4*)&ea[(size_t)e * EDGE_IN + 4 * lane];
            d[256 + 4 * lane + 0] = tf32r(c.x); d[256 + 4 * lane + 1] = tf32r(c.y);
            d[256 + 4 * lane + 2] = tf32r(c.z); d[256 + 4 * lane + 3] = tf32r(c.w);
        }
    }
    __syncthreads();

    float acc[2][8][4];
#pragma unroll
    for (int mt = 0; mt < 2; mt++)
#pragma unroll
        for (int j = 0; j < 8; j++) {
            int col = nh * 64 + j * 8 + 2 * tig;
            acc[mt][j][0] = sb1[col]; acc[mt][j][1] = sb1[col + 1];
            acc[mt][j][2] = sb1[col]; acc[mt][j][3] = sb1[col + 1];
        }
    // ---- GEMM1: K = 272 = 34 k8-steps ----
    for (int k8 = 0; k8 < K8_1; k8++) {
        cp_wait<0>(); __syncthreads();
        if (k8 + 1 < K8_1) {
            float* db = wb + ((k8 + 1) & 1) * 2048;
            cp16(db + tid * 4, w1h + (k8 + 1) * 1024 + tid * 4);
            cp16(db + 1024 + tid * 4, w1l + (k8 + 1) * 1024 + tid * 4);
            cp_commit();
        }
        const float* wc = wb + (k8 & 1) * 2048;
        int kb = k8 * 8 + tig;
        unsigned A[2][4];
#pragma unroll
        for (int mt = 0; mt < 2; mt++) {
            int r = wg * 32 + mt * 16 + gid;
            A[mt][0] = __float_as_uint(s_in[r * ASTR + kb]);
            A[mt][1] = __float_as_uint(s_in[(r + 8) * ASTR + kb]);
            A[mt][2] = __float_as_uint(s_in[r * ASTR + kb + 4]);
            A[mt][3] = __float_as_uint(s_in[(r + 8) * ASTR + kb + 4]);
        }
#pragma unroll
        for (int j = 0; j < 8; j++) {
            int nt = nh * 8 + j;
            float2 bh = *(const float2*)&wc[(nt * 32 + lane) * 2];
            float2 bl = *(const float2*)&wc[1024 + (nt * 32 + lane) * 2];
            mma8(acc[0][j], A[0], bh); mma8(acc[0][j], A[0], bl);
            mma8(acc[1][j], A[1], bh); mma8(acc[1][j], A[1], bl);
        }
    }
    __syncthreads();                  // all s_in reads done
    // stage W2 chunk 0 into buffer 0 (last W1 chunk was buffer 1)
    cp16(wb + tid * 4, w2h + tid * 4);
    cp16(wb + 1024 + tid * 4, w2l + tid * 4);
    cp_commit();
    // epilogue1: relu(acc) -> s_hid (tf32-rounded), stride HSTR
#pragma unroll
    for (int mt = 0; mt < 2; mt++) {
        int r0 = wg * 32 + mt * 16 + gid;
#pragma unroll
        for (int j = 0; j < 8; j++) {
            int col = nh * 64 + j * 8 + 2 * tig;
            float2 v0, v1;
            v0.x = tf32r(fmaxf(acc[mt][j][0], 0.f)); v0.y = tf32r(fmaxf(acc[mt][j][1], 0.f));
            v1.x = tf32r(fmaxf(acc[mt][j][2], 0.f)); v1.y = tf32r(fmaxf(acc[mt][j][3], 0.f));
            *(float2*)&s_hid[r0 * HSTR + col] = v0;
            *(float2*)&s_hid[(r0 + 8) * HSTR + col] = v1;
        }
    }
#pragma unroll
    for (int mt = 0; mt < 2; mt++)
#pragma unroll
        for (int j = 0; j < 8; j++) {
            acc[mt][j][0] = 0.f; acc[mt][j][1] = 0.f; acc[mt][j][2] = 0.f; acc[mt][j][3] = 0.f;
        }
    __syncthreads();                  // s_hid visible
    // ---- GEMM2: K = 128 = 16 k8-steps ----
    for (int k8 = 0; k8 < K8_2; k8++) {
        cp_wait<0>(); __syncthreads();
        if (k8 + 1 < K8_2) {
            float* db = wb + ((k8 + 1) & 1) * 2048;
            cp16(db + tid * 4, w2h + (k8 + 1) * 1024 + tid * 4);
            cp16(db + 1024 + tid * 4, w2l + (k8 + 1) * 1024 + tid * 4);
            cp_commit();
        }
        const float* wc = wb + (k8 & 1) * 2048;
        int kb = k8 * 8 + tig;
        unsigned A[2][4];
#pragma unroll
        for (int mt = 0; mt < 2; mt++) {
            int r = wg * 32 + mt * 16 + gid;
            A[mt][0] = __float_as_uint(s_hid[r * HSTR + kb]);
            A[mt][1] = __float_as_uint(s_hid[(r + 8) * HSTR + kb]);
            A[mt][2] = __float_as_uint(s_hid[r * HSTR + kb + 4]);
            A[mt][3] = __float_as_uint(s_hid[(r + 8) * HSTR + kb + 4]);
        }
#pragma unroll
        for (int j = 0; j < 8; j++) {
            int nt = nh * 8 + j;
            float2 bh = *(const float2*)&wc[(nt * 32 + lane) * 2];
            float2 bl = *(const float2*)&wc[1024 + (nt * 32 + lane) * 2];
            mma8(acc[0][j], A[0], bh); mma8(acc[0][j], A[0], bl);
            mma8(acc[1][j], A[1], bh); mma8(acc[1][j], A[1], bl);
        }
    }
    // epilogue2: +b2, scatter-add (mean numerator)
#pragma unroll
    for (int mt = 0; mt < 2; mt++) {
        int r0 = wg * 32 + mt * 16 + gid;
        int t0 = s_t[r0], t1 = s_t[r0 + 8];
#pragma unroll
        for (int j = 0; j < 8; j++) {
            int col = nh * 64 + j * 8 + 2 * tig;
            float2 v0 = make_float2(acc[mt][j][0] + sb2[col], acc[mt][j][1] + sb2[col + 1]);
            float2 v1 = make_float2(acc[mt][j][2] + sb2[col], acc[mt][j][3] + sb2[col + 1]);
            red2(&g_aggr[(size_t)t0 * HIDN + col], v0);
            red2(&g_aggr[(size_t)t1 * HIDN + col], v1);
        }
    }
}
// ============================================================================
// node update (proven R4): 64 nodes/block, 128 threads, FFMA2
// ============================================================================
#define UPD_SMEM (64*256*4 + 2*2048*4)
__global__ void __launch_bounds__(128) update_kernel2(
        const float* W1, const float* b1, const float* W2, const float* b2,
        const float* gw, const float* gb) {
    extern __shared__ float sm[];
    float* s_in = sm; float* wb = sm + 64 * 256; float* s_hid = sm;
    int tid = threadIdx.x, lane = tid & 31, warp = tid >> 5;
    int nb = blockIdx.x * 64;
    stage_w128(wb, W1, tid); cp_commit();
    for (int j = warp; j < 64; j += 4) {
        int n = nb + j;
        if (n < NND) {
            float inv = g_invd[n];
            float4 hv = *(const float4*)&g_h[n * HIDN + 4 * lane];
            float4 av = *(const float4*)&g_aggr[n * HIDN + 4 * lane];
            av.x *= inv; av.y *= inv; av.z *= inv; av.w *= inv;
            *(float4*)&s_in[j * 256 + 4 * lane] = hv;
            *(float4*)&s_in[j * 256 + 128 + 4 * lane] = av;
        } else {
            *(float4*)&s_in[j * 256 + 4 * lane] = make_float4(0.f, 0.f, 0.f, 0.f);
            *(float4*)&s_in[j * 256 + 128 + 4 * lane] = make_float4(0.f, 0.f, 0.f, 0.f);
        }
    }
    int cg = tid & 15, egp = tid >> 4, c0 = 8 * cg, e0 = 8 * egp;
    ull acc[8][4];
    {
        ulonglong2 bA = *(const ulonglong2*)(b1 + c0), bB = *(const ulonglong2*)(b1 + c0 + 4);
#pragma unroll
        for (int i = 0; i < 8; i++) { acc[i][0] = bA.x; acc[i][1] = bA.y; acc[i][2] = bB.x; acc[i][3] = bB.y; }
    }
    for (int c = 0; c < 16; c++) {
        cp_wait<0>(); __syncthreads();
        if (c < 15) { stage_w128(wb + ((c + 1) & 1) * 2048, W1 + (c + 1) * 2048, tid); cp_commit(); }
        const float* wv = wb + (c & 1) * 2048; int kb = c * 16;
#pragma unroll
        for (int k4 = 0; k4 < 16; k4 += 4) {
            float4 av[8];
#pragma unroll
            for (int i = 0; i < 8; i++) av[i] = *(const float4*)&s_in[(e0 + i) * 256 + kb + k4];
#pragma unroll
            for (int kk = 0; kk < 4; kk++) {
                const float* wr = wv + (k4 + kk) * 128 + c0;
                ulonglong2 w0 = *(const ulonglong2*)(wr), w1 = *(const ulonglong2*)(wr + 4);
#pragma unroll
                for (int i = 0; i < 8; i++) {
                    float a = (kk == 0) ? av[i].x : (kk == 1) ? av[i].y : (kk == 2) ? av[i].z : av[i].w;
                    ull adp = dup2(a);
                    acc[i][0] = fma2(adp, w0.x, acc[i][0]); acc[i][1] = fma2(adp, w0.y, acc[i][1]);
                    acc[i][2] = fma2(adp, w1.x, acc[i][2]); acc[i][3] = fma2(adp, w1.y, acc[i][3]);
                }
            }
        }
    }
    __syncthreads();
    stage_w128(wb, W2, tid); cp_commit();
#pragma unroll
    for (int i = 0; i < 8; i++) {
        float2 p0 = unpack2(acc[i][0]), p1 = unpack2(acc[i][1]);
        float2 p2 = unpack2(acc[i][2]), p3 = unpack2(acc[i][3]);
        *(float4*)&s_hid[(e0 + i) * 128 + c0] =
            make_float4(fmaxf(p0.x, 0.f), fmaxf(p0.y, 0.f), fmaxf(p1.x, 0.f), fmaxf(p1.y, 0.f));
        *(float4*)&s_hid[(e0 + i) * 128 + c0 + 4] =
            make_float4(fmaxf(p2.x, 0.f), fmaxf(p2.y, 0.f), fmaxf(p3.x, 0.f), fmaxf(p3.y, 0.f));
    }
    ull acc2[8][4];
    {
        ulonglong2 bA = *(const ulonglong2*)(b2 + c0), bB = *(const ulonglong2*)(b2 + c0 + 4);
#pragma unroll
        for (int i = 0; i < 8; i++) { acc2[i][0] = bA.x; acc2[i][1] = bA.y; acc2[i][2] = bB.x; acc2[i][3] = bB.y; }
    }
    for (int c = 0; c < 8; c++) {
        cp_wait<0>(); __syncthreads();
        if (c < 7) { stage_w128(wb + ((c + 1) & 1) * 2048, W2 + (c + 1) * 2048, tid); cp_commit(); }
        const float* wv = wb + (c & 1) * 2048; int kb = c * 16;
#pragma unroll
        for (int k4 = 0; k4 < 16; k4 += 4) {
            float4 av[8];
#pragma unroll
            for (int i = 0; i < 8; i++) av[i] = *(const float4*)&s_hid[(e0 + i) * 128 + kb + k4];
#pragma unroll
            for (int kk = 0; kk < 4; kk++) {
                const float* wr = wv + (k4 + kk) * 128 + c0;
                ulonglong2 w0 = *(const ulonglong2*)(wr), w1 = *(const ulonglong2*)(wr + 4);
#pragma unroll
                for (int i = 0; i < 8; i++) {
                    float a = (kk == 0) ? av[i].x : (kk == 1) ? av[i].y : (kk == 2) ? av[i].z : av[i].w;
                    ull adp = dup2(a);
                    acc2[i][0] = fma2(adp, w0.x, acc2[i][0]); acc2[i][1] = fma2(adp, w0.y, acc2[i][1]);
                    acc2[i][2] = fma2(adp, w1.x, acc2[i][2]); acc2[i][3] = fma2(adp, w1.y, acc2[i][3]);
                }
            }
        }
    }
    float4 g0 = *(const float4*)&gw[c0], g1 = *(const float4*)&gw[c0 + 4];
    float4 bb0 = *(const float4*)&gb[c0], bb1 = *(const float4*)&gb[c0 + 4];
#pragma unroll
    for (int i = 0; i < 8; i++) {
        int n = nb + e0 + i;
        float2 p0 = unpack2(acc2[i][0]), p1 = unpack2(acc2[i][1]);
        float2 p2 = unpack2(acc2[i][2]), p3 = unpack2(acc2[i][3]);
        float4 h0 = make_float4(0.f, 0.f, 0.f, 0.f), h1 = h0;
        if (n < NND) { h0 = *(const float4*)&g_h[n * HIDN + c0]; h1 = *(const float4*)&g_h[n * HIDN + c0 + 4]; }
        float o[8];
        o[0] = p0.x + h0.x; o[1] = p0.y + h0.y; o[2] = p1.x + h0.z; o[3] = p1.y + h0.w;
        o[4] = p2.x + h1.x; o[5] = p2.y + h1.y; o[6] = p3.x + h1.z; o[7] = p3.y + h1.w;
        float s = 0.f, q = 0.f;
#pragma unroll
        for (int k = 0; k < 8; k++) { s += o[k]; q += o[k] * o[k]; }
#pragma unroll
        for (int off = 1; off < 16; off <<= 1) {
            s += __shfl_xor_sync(0xffffffffu, s, off);
            q += __shfl_xor_sync(0xffffffffu, q, off);
        }
        float mean = s * (1.f / 128.f), var = q * (1.f / 128.f) - mean * mean;
        float rs = rsqrtf(var + 1e-5f);
        if (n < NND) {
            float4 r0, r1;
            r0.x = (o[0] - mean) * rs * g0.x + bb0.x; r0.y = (o[1] - mean) * rs * g0.y + bb0.y;
            r0.z = (o[2] - mean) * rs * g0.z + bb0.z; r0.w = (o[3] - mean) * rs * g0.w + bb0.w;
            r1.x = (o[4] - mean) * rs * g1.x + bb1.x; r1.y = (o[5] - mean) * rs * g1.y + bb1.y;
            r1.z = (o[6] - mean) * rs * g1.z + bb1.z; r1.w = (o[7] - mean) * rs * g1.w + bb1.w;
            *(float4*)&g_h[n * HIDN + c0] = r0;
            *(float4*)&g_h[n * HIDN + c0 + 4] = r1;
            *(float4*)&g_aggr[n * HIDN + c0] = make_float4(0.f, 0.f, 0.f, 0.f);
            *(float4*)&g_aggr[n * HIDN + c0 + 4] = make_float4(0.f, 0.f, 0.f, 0.f);
        }
    }
}
// ---------- encoder / head ----------
__device__ __forceinline__ void ln_store(float (*s_out)[HPAD], int nb, const float* gw, const float* gb) {
    int tid = threadIdx.x, nn = tid >> 3, p = tid & 7, n = nb + nn;
    float vals[16], sum = 0.f, sq = 0.f;
#pragma unroll
    for (int i = 0; i < 4; i++) {
        float4 t4 = *(float4*)&s_out[nn][16 * p + 4 * i];
        vals[4*i+0] = t4.x; vals[4*i+1] = t4.y; vals[4*i+2] = t4.z; vals[4*i+3] = t4.w;
        sum += t4.x + t4.y + t4.z + t4.w;
        sq += t4.x*t4.x + t4.y*t4.y + t4.z*t4.z + t4.w*t4.w;
    }
#pragma unroll
    for (int off = 4; off; off >>= 1) {
        sum += __shfl_xor_sync(0xffffffffu, sum, off);
        sq  += __shfl_xor_sync(0xffffffffu, sq, off);
    }
    float mean = sum * (1.f / 128.f), var = sq * (1.f / 128.f) - mean * mean;
    float rs = rsqrtf(var + 1e-5f);
    if (n < NND) {
#pragma unroll
        for (int i = 0; i < 4; i++) {
            int c = 16 * p + 4 * i; float4 o;
            o.x = (vals[4*i+0] - mean) * rs * gw[c+0] + gb[c+0];
            o.y = (vals[4*i+1] - mean) * rs * gw[c+1] + gb[c+1];
            o.z = (vals[4*i+2] - mean) * rs * gw[c+2] + gb[c+2];
            o.w = (vals[4*i+3] - mean) * rs * gw[c+3] + gb[c+3];
            *(float4*)&g_h[n * HIDN + c] = o;
        }
    }
}
__global__ __launch_bounds__(256) void encoder_kernel(const float* x, const float* W,
        const float* b, const float* gw, const float* gb) {
    __shared__ float s_in[TN][XPAD];
    __shared__ float s_out[TN][HPAD];
    int tid = threadIdx.x, lane = tid & 31, w = tid >> 5;
    int nb = blockIdx.x * TN;
    for (int j = w; j < TN; j += 8) {
        int n = nb + j;
        if (lane < 8) {
            float4 v = make_float4(0.f, 0.f, 0.f, 0.f);
            if (n < NND) v = *(const float4*)&x[n * NODE_IN + 4 * lane];
            *(float4*)&s_in[j][4 * lane] = v;
        }
    }
    __syncthreads();
    int cg = tid & 31, c0 = 4 * cg, eg = tid >> 5, e0 = 4 * eg;
    ull acc[4][2];
    {
        ull b01 = *(const ull*)(b + c0), b23 = *(const ull*)(b + c0 + 2);
#pragma unroll
        for (int i = 0; i < 4; i++) { acc[i][0] = b01; acc[i][1] = b23; }
    }
#pragma unroll
    for (int k = 0; k < NODE_IN; k++) {
        ulonglong2 wv = *(const ulonglong2*)(W + k * HIDN + c0);
#pragma unroll
        for (int i = 0; i < 4; i++) {
            ull a = dup2(s_in[e0 + i][k]);
            acc[i][0] = fma2(a, wv.x, acc[i][0]); acc[i][1] = fma2(a, wv.y, acc[i][1]);
        }
    }
#pragma unroll
    for (int i = 0; i < 4; i++) {
        float2 v0 = unpack2(acc[i][0]), v1 = unpack2(acc[i][1]);
        s_out[e0 + i][c0 + 0] = fmaxf(v0.x, 0.f); s_out[e0 + i][c0 + 1] = fmaxf(v0.y, 0.f);
        s_out[e0 + i][c0 + 2] = fmaxf(v1.x, 0.f); s_out[e0 + i][c0 + 3] = fmaxf(v1.y, 0.f);
    }
    __syncthreads();
    ln_store(s_out, nb, gw, gb);
}
__global__ __launch_bounds__(256) void head_kernel(const float* W, const float* b, float* out) {
    __shared__ float s_in[TN][HPAD];
    int tid = threadIdx.x, lane = tid & 31, w = tid >> 5;
    int nb = blockIdx.x * TN;
    for (int j = w; j < TN; j += 8) {
        int n = nb + j;
        float4 v = make_float4(0.f, 0.f, 0.f, 0.f);
        if (n < NND) v = *(const float4*)&g_h[n * HIDN + 4 * lane];
        *(float4*)&s_in[j][4 * lane] = v;
    }
    __syncthreads();
    int cg = tid & 31, c0 = 4 * cg, eg = tid >> 5, e0 = 4 * eg;
    ull acc[4][2];
    {
        ull b01 = *(const ull*)(b + c0), b23 = *(const ull*)(b + c0 + 2);
#pragma unroll
        for (int i = 0; i < 4; i++) { acc[i][0] = b01; acc[i][1] = b23; }
    }
#pragma unroll 4
    for (int k = 0; k < HIDN; k++) {
        ulonglong2 wv = *(const ulonglong2*)(W + k * HIDN + c0);
#pragma unroll
        for (int i = 0; i < 4; i++) {
            ull a = dup2(s_in[e0 + i][k]);
            acc[i][0] = fma2(a, wv.x, acc[i][0]); acc[i][1] = fma2(a, wv.y, acc[i][1]);
        }
    }
#pragma unroll
    for (int i = 0; i < 4; i++) {
        int n = nb + e0 + i;
        if (n < NND) {
            float2 v0 = unpack2(acc[i][0]), v1 = unpack2(acc[i][1]);
            *(float2*)&out[n * HIDN + c0 + 0] = v0;
            *(float2*)&out[n * HIDN + c0 + 2] = v1;
        }
    }
}
// ---------- launch ----------
extern "C" void kernel_launch(void* const* d_in, const int* in_sizes, int n_in,
                              void* d_out, int out_size) {
    const float* x      = (const float*)d_in[0];
    const void*  ei     = d_in[1];
    const float* ea     = (const float*)d_in[2];
    const float* enc_W  = (const float*)d_in[3];
    const float* enc_b  = (const float*)d_in[4];
    const float* enc_g  = (const float*)d_in[5];
    const float* enc_be = (const float*)d_in[6];
    const float* msg_W1 = (const float*)d_in[7];
    const float* msg_b1 = (const float*)d_in[8];
    const float* msg_W2 = (const float*)d_in[9];
    const float* msg_b2 = (const float*)d_in[10];
    const float* upd_W1 = (const float*)d_in[11];
    const float* upd_b1 = (const float*)d_in[12];
    const float* upd_W2 = (const float*)d_in[13];
    const float* upd_b2 = (const float*)d_in[14];
    const float* ln_g   = (const float*)d_in[15];
    const float* ln_be  = (const float*)d_in[16];
    const float* head_W = (const float*)d_in[17];
    const float* head_b = (const float*)d_in[18];
    float* out = (float*)d_out;

    cudaFuncSetAttribute(edge_mma, cudaFuncAttributeMaxDynamicSharedMemorySize, EK_SMEM);
    cudaFuncSetAttribute(update_kernel2, cudaFuncAttributeMaxDynamicSharedMemorySize, UPD_SMEM);

    init_kernel<<<256, 256>>>();
    detect_kernel<<<256, 256>>>((const unsigned*)ei);
    count_kernel<<<512, 256>>>(ei);
    inv_kernel<<<(NND + 255) / 256, 256>>>();
    pack_w1f<<<(2 * K8_1 * 512 + 255) / 256, 256>>>(msg_W1);
    pack_w2f<<<(2 * K8_2 * 512 + 255) / 256, 256>>>(msg_W2);

    int nblk32 = (NND + TN - 1) / TN, nblk64 = (NND + 63) / 64;
    encoder_kernel<<<nblk32, 256>>>(x, enc_W, enc_b, enc_g, enc_be);
    for (int l = 0; l < 2; l++) {
        edge_mma<<<NE / 128, 256, EK_SMEM>>>(ei, ea, msg_b1 + l * HIDN, msg_b2 + l * HIDN, l);
        update_kernel2<<<nblk64, 128, UPD_SMEM>>>(upd_W1 + l * UIN * HIDN, upd_b1 + l * HIDN,
                upd_W2 + l * HIDN * HIDN, upd_b2 + l * HIDN, ln_g + l * HIDN, ln_be + l * HIDN);
    }
    head_kernel<<<nblk32, 256>>>(head_W, head_b, out);
}

// round 8
// speedup vs baseline: 1.8334x; 1.2237x over previous
#include <cuda_runtime.h>
#include <math.h>
#include <stdint.h>

#define NND 50000
#define NE  800000
#define HIDN 128
#define NODE_IN 32
#define EDGE_IN 16
#define CIN 272
#define UIN 256
#define HPAD 132
#define XPAD 36
#define TN 32
#define K8_1P 36
#define K8_2 16
#define W1F (K8_1P*1024)
#define W2F (K8_2*1024)
#define ASTR 292
#define HSTR 132

typedef unsigned long long ull;

__device__ float g_h[NND * HIDN];
__device__ float g_aggr[NND * HIDN];
__device__ float g_invd[NND];
__device__ int   g_cnt[NND];
__device__ int   g_is64;
__device__ __align__(16) float g_w1h[2 * W1F];
__device__ __align__(16) float g_w2h[2 * W2F];

// ---------- tf32 round-to-nearest ----------
__device__ __forceinline__ float tf32r(float x) {
    unsigned u; asm("cvt.rna.tf32.f32 %0, %1;" : "=r"(u) : "f"(x));
    return __uint_as_float(u);
}
// ---------- f32x2 (node kernels) ----------
__device__ __forceinline__ ull fma2(ull a, ull b, ull c) {
    ull d; asm("fma.rn.f32x2 %0, %1, %2, %3;" : "=l"(d) : "l"(a), "l"(b), "l"(c)); return d;
}
__device__ __forceinline__ ull dup2(float a) {
    ull d; unsigned r = __float_as_uint(a);
    asm("mov.b64 %0, {%1, %1};" : "=l"(d) : "r"(r)); return d;
}
__device__ __forceinline__ float2 unpack2(ull v) {
    unsigned lo, hi; asm("mov.b64 {%0, %1}, %2;" : "=r"(lo), "=r"(hi) : "l"(v));
    return make_float2(__uint_as_float(lo), __uint_as_float(hi));
}
// ---------- cp.async ----------
__device__ __forceinline__ void cp16(float* dst, const float* src) {
    unsigned d = (unsigned)__cvta_generic_to_shared(dst);
    asm volatile("cp.async.ca.shared.global [%0], [%1], 16;" :: "r"(d), "l"(src));
}
__device__ __forceinline__ void cp_commit() { asm volatile("cp.async.commit_group;"); }
template<int N> __device__ __forceinline__ void cp_wait() {
    asm volatile("cp.async.wait_group %0;" :: "n"(N));
}
// stage 4096 floats (16KB) with 256 threads
__device__ __forceinline__ void stage_w128(float* dst, const float* src, int tid) {
    int o = tid * 16;
    cp16(dst + o, src + o); cp16(dst + o + 4, src + o + 4);
    cp16(dst + o + 8, src + o + 8); cp16(dst + o + 12, src + o + 12);
}
// ---------- global reductions ----------
__device__ __forceinline__ void red2(float* a, float2 v) {
    asm volatile("red.global.add.v2.f32 [%0], {%1, %2};"
                 :: "l"(a), "f"(v.x), "f"(v.y) : "memory");
}
// ---------- tf32 mma ----------
__device__ __forceinline__ void mma8(float* c, const unsigned* a, float2 b) {
    asm volatile("mma.sync.aligned.m16n8k8.row.col.f32.tf32.tf32.f32 "
        "{%0,%1,%2,%3}, {%4,%5,%6,%7}, {%8,%9}, {%0,%1,%2,%3};"
        : "+f"(c[0]), "+f"(c[1]), "+f"(c[2]), "+f"(c[3])
        : "r"(a[0]), "r"(a[1]), "r"(a[2]), "r"(a[3]),
          "r"(__float_as_uint(b.x)), "r"(__float_as_uint(b.y)));
}
// ---------- edge index ----------
__device__ __forceinline__ void load_edge(const void* ei, int e, int& s, int& t) {
    if (g_is64) { const long long* p = (const long long*)ei; s = (int)p[e]; t = (int)p[NE + e]; }
    else        { const int* p = (const int*)ei;             s = p[e];      t = p[NE + e]; }
}
// ---------- setup ----------
__global__ void init_kernel() {
    int i = blockIdx.x * blockDim.x + threadIdx.x, st = gridDim.x * blockDim.x;
    if (i == 0) g_is64 = 1;
    for (int j = i; j < NND; j += st) g_cnt[j] = 0;
    for (int j = i; j < NND * HIDN; j += st) g_aggr[j] = 0.f;
}
__global__ void detect_kernel(const unsigned* w) {
    int st = gridDim.x * blockDim.x; bool nz = false;
    for (int i = blockIdx.x * blockDim.x + threadIdx.x; i < NE; i += st) nz |= (w[2 * i + 1] != 0u);
    if (nz) g_is64 = 0;
}
__global__ void count_kernel(const void* ei) {
    int st = gridDim.x * blockDim.x;
    for (int e = blockIdx.x * blockDim.x + threadIdx.x; e < NE; e += st) {
        int s, t; load_edge(ei, e, s, t); atomicAdd(&g_cnt[t], 1);
    }
}
__global__ void inv_kernel() {
    int n = blockIdx.x * blockDim.x + threadIdx.x;
    if (n < NND) g_invd[n] = 1.f / fmaxf((float)g_cnt[n], 1.f);
}
// ---------- weight packing: B-fragment order, tf32 (rna) ----------
// per layer: [k8][nt(16)][lane(32)][2]; b0=W[k8*8+tig][nt*8+gid], b1=W[k+4][n]
__global__ void pack_w1f(const float* W1) {
    int i = blockIdx.x * blockDim.x + threadIdx.x;
    if (i >= 2 * K8_1P * 512) return;
    int lane = i & 31, r = i >> 5;
    int nt = r & 15; r >>= 4;
    int k8 = r % K8_1P, l = r / K8_1P;
    int gid = lane >> 2, tig = lane & 3;
    int n = nt * 8 + gid;
    int k0 = k8 * 8 + tig, k1 = k0 + 4;
    float v0 = (k0 < CIN) ? W1[(l * CIN + k0) * 128 + n] : 0.f;
    float v1 = (k1 < CIN) ? W1[(l * CIN + k1) * 128 + n] : 0.f;
    int off = l * W1F + ((k8 * 16 + nt) * 32 + lane) * 2;
    g_w1h[off] = tf32r(v0); g_w1h[off + 1] = tf32r(v1);
}
__global__ void pack_w2f(const float* W2) {
    int i = blockIdx.x * blockDim.x + threadIdx.x;
    if (i >= 2 * K8_2 * 512) return;
    int lane = i & 31, r = i >> 5;
    int nt = r & 15; r >>= 4;
    int k8 = r % K8_2, l = r / K8_2;
    int gid = lane >> 2, tig = lane & 3;
    int n = nt * 8 + gid;
    int k0 = k8 * 8 + tig, k1 = k0 + 4;
    float v0 = W2[(l * 128 + k0) * 128 + n];
    float v1 = W2[(l * 128 + k1) * 128 + n];
    int off = l * W2F + ((k8 * 16 + nt) * 32 + lane) * 2;
    g_w2h[off] = tf32r(v0); g_w2h[off + 1] = tf32r(v1);
}
// ============================================================================
// tf32 mma.sync edge kernel: 64 edges/CTA, 256 threads (8 warps), 2 CTAs/SM.
// warp = (wg = 16-edge group, nh = 64-col half). 1 m-tile x 8 n-tiles.
// K chunked 4 k8-steps per cp.async stage (16KB x2 buffers).
// SMEM: s_t[64]@0 | sb1@512 | sb2@1024 | s_in[64][292]@1536 | wb[2][4096]
// ============================================================================
#define EK_SMEM (1536 + 64*ASTR*4 + 2*4096*4)

__global__ void __launch_bounds__(256) edge_mma(const void* ei, const float* ea,
        const float* b1v, const float* b2v, int layer) {
    extern __shared__ char smc[];
    int*   s_t  = (int*)smc;
    float* sb1  = (float*)(smc + 512);
    float* sb2  = (float*)(smc + 1024);
    float* s_in = (float*)(smc + 1536);
    float* s_hid = s_in;                       // stride HSTR, alias
    float* wb   = (float*)(smc + 1536 + 64 * ASTR * 4);   // [2][4096]
    const float* w1h = g_w1h + layer * W1F;
    const float* w2h = g_w2h + layer * W2F;

    int tid = threadIdx.x, lane = tid & 31, warp = tid >> 5;
    int wg = warp >> 1, nh = warp & 1;
    int gid = lane >> 2, tig = lane & 3;
    int r0 = wg * 16 + gid, r1 = r0 + 8;
    int eb = blockIdx.x * 64;

    if (tid < 128) { sb1[tid] = b1v[tid]; sb2[tid] = b2v[tid]; }
    // stage W1 chunk 0 (4 k8 = 16KB)
    stage_w128(wb, w1h, tid); cp_commit();
    // zero K-pad cols 272..287
    for (int idx = tid; idx < 64 * 16; idx += 256)
        s_in[(idx >> 4) * ASTR + 272 + (idx & 15)] = 0.f;
    // gather [x_i | x_j | ea], tf32-rounded
    for (int j = warp; j < 64; j += 8) {
        int e = eb + j, s, t; load_edge(ei, e, s, t);
        if (lane == 0) s_t[j] = t;
        float* d = s_in + j * ASTR;
        float4 a = *(const float4*)&g_h[(size_t)t * HIDN + 4 * lane];
        d[4 * lane + 0] = tf32r(a.x); d[4 * lane + 1] = tf32r(a.y);
        d[4 * lane + 2] = tf32r(a.z); d[4 * lane + 3] = tf32r(a.w);
        float4 b = *(const float4*)&g_h[(size_t)s * HIDN + 4 * lane];
        d[128 + 4 * lane + 0] = tf32r(b.x); d[128 + 4 * lane + 1] = tf32r(b.y);
        d[128 + 4 * lane + 2] = tf32r(b.z); d[128 + 4 * lane + 3] = tf32r(b.w);
        if (lane < 4) {
            float4 c = *(const float4*)&ea[(size_t)e * EDGE_IN + 4 * lane];
            d[256 + 4 * lane + 0] = tf32r(c.x); d[256 + 4 * lane + 1] = tf32r(c.y);
            d[256 + 4 * lane + 2] = tf32r(c.z); d[256 + 4 * lane + 3] = tf32r(c.w);
        }
    }
    __syncthreads();

    float acc[8][4];
#pragma unroll
    for (int j = 0; j < 8; j++) {
        int col = nh * 64 + j * 8 + 2 * tig;
        acc[j][0] = sb1[col]; acc[j][1] = sb1[col + 1];
        acc[j][2] = sb1[col]; acc[j][3] = sb1[col + 1];
    }
    // ---- GEMM1: K = 288 (padded) = 9 chunks x 4 k8 ----
    for (int ch = 0; ch < 9; ch++) {
        cp_wait<0>(); __syncthreads();
        if (ch < 8) { stage_w128(wb + ((ch + 1) & 1) * 4096, w1h + (ch + 1) * 4096, tid); cp_commit(); }
        const float* wc0 = wb + (ch & 1) * 4096;
#pragma unroll
        for (int q = 0; q < 4; q++) {
            int kb = (ch * 4 + q) * 8 + tig;
            unsigned A[4];
            A[0] = __float_as_uint(s_in[r0 * ASTR + kb]);
            A[1] = __float_as_uint(s_in[r1 * ASTR + kb]);
            A[2] = __float_as_uint(s_in[r0 * ASTR + kb + 4]);
            A[3] = __float_as_uint(s_in[r1 * ASTR + kb + 4]);
#pragma unroll
            for (int j = 0; j < 8; j++) {
                float2 bh = *(const float2*)&wc0[q * 1024 + ((nh * 8 + j) * 32 + lane) * 2];
                mma8(acc[j], A, bh);
            }
        }
    }
    __syncthreads();                  // all s_in + buf reads done
    // stage W2 chunk 0 into buf0
    stage_w128(wb, w2h, tid); cp_commit();
    // epilogue1: relu(acc) -> s_hid (tf32-rounded), stride HSTR
#pragma unroll
    for (int j = 0; j < 8; j++) {
        int col = nh * 64 + j * 8 + 2 * tig;
        float2 v0, v1;
        v0.x = tf32r(fmaxf(acc[j][0], 0.f)); v0.y = tf32r(fmaxf(acc[j][1], 0.f));
        v1.x = tf32r(fmaxf(acc[j][2], 0.f)); v1.y = tf32r(fmaxf(acc[j][3], 0.f));
        *(float2*)&s_hid[r0 * HSTR + col] = v0;
        *(float2*)&s_hid[r1 * HSTR + col] = v1;
        acc[j][0] = 0.f; acc[j][1] = 0.f; acc[j][2] = 0.f; acc[j][3] = 0.f;
    }
    // ---- GEMM2: K = 128 = 4 chunks x 4 k8 ----
    for (int ch = 0; ch < 4; ch++) {
        cp_wait<0>(); __syncthreads();   // first iter also publishes s_hid
        if (ch < 3) { stage_w128(wb + ((ch + 1) & 1) * 4096, w2h + (ch + 1) * 4096, tid); cp_commit(); }
        const float* wc0 = wb + (ch & 1) * 4096;
#pragma unroll
        for (int q = 0; q < 4; q++) {
            int kb = (ch * 4 + q) * 8 + tig;
            unsigned A[4];
            A[0] = __float_as_uint(s_hid[r0 * HSTR + kb]);
            A[1] = __float_as_uint(s_hid[r1 * HSTR + kb]);
            A[2] = __float_as_uint(s_hid[r0 * HSTR + kb + 4]);
            A[3] = __float_as_uint(s_hid[r1 * HSTR + kb + 4]);
#pragma unroll
            for (int j = 0; j < 8; j++) {
                float2 bh = *(const float2*)&wc0[q * 1024 + ((nh * 8 + j) * 32 + lane) * 2];
                mma8(acc[j], A, bh);
            }
        }
    }
    // epilogue2: +b2, scatter-add (mean numerator)
    int t0 = s_t[r0], t1 = s_t[r1];
#pragma unroll
    for (int j = 0; j < 8; j++) {
        int col = nh * 64 + j * 8 + 2 * tig;
        red2(&g_aggr[(size_t)t0 * HIDN + col],
             make_float2(acc[j][0] + sb2[col], acc[j][1] + sb2[col + 1]));
        red2(&g_aggr[(size_t)t1 * HIDN + col],
             make_float2(acc[j][2] + sb2[col], acc[j][3] + sb2[col + 1]));
    }
}
// ============================================================================
// node update (proven R4): 64 nodes/block, 128 threads, FFMA2
// ============================================================================
#define UPD_SMEM (64*256*4 + 2*2048*4)
__device__ __forceinline__ void stage_half(float* dst, const float* src, int tid) {
    int o = tid * 16;
    cp16(dst + o, src + o); cp16(dst + o + 4, src + o + 4);
    cp16(dst + o + 8, src + o + 8); cp16(dst + o + 12, src + o + 12);
}
__global__ void __launch_bounds__(128) update_kernel2(
        const float* W1, const float* b1, const float* W2, const float* b2,
        const float* gw, const float* gb) {
    extern __shared__ float sm[];
    float* s_in = sm; float* wb = sm + 64 * 256; float* s_hid = sm;
    int tid = threadIdx.x, lane = tid & 31, warp = tid >> 5;
    int nb = blockIdx.x * 64;
    stage_half(wb, W1, tid); cp_commit();
    for (int j = warp; j < 64; j += 4) {
        int n = nb + j;
        if (n < NND) {
            float inv = g_invd[n];
            float4 hv = *(const float4*)&g_h[n * HIDN + 4 * lane];
            float4 av = *(const float4*)&g_aggr[n * HIDN + 4 * lane];
            av.x *= inv; av.y *= inv; av.z *= inv; av.w *= inv;
            *(float4*)&s_in[j * 256 + 4 * lane] = hv;
            *(float4*)&s_in[j * 256 + 128 + 4 * lane] = av;
        } else {
            *(float4*)&s_in[j * 256 + 4 * lane] = make_float4(0.f, 0.f, 0.f, 0.f);
            *(float4*)&s_in[j * 256 + 128 + 4 * lane] = make_float4(0.f, 0.f, 0.f, 0.f);
        }
    }
    int cg = tid & 15, egp = tid >> 4, c0 = 8 * cg, e0 = 8 * egp;
    ull acc[8][4];
    {
        ulonglong2 bA = *(const ulonglong2*)(b1 + c0), bB = *(const ulonglong2*)(b1 + c0 + 4);
#pragma unroll
        for (int i = 0; i < 8; i++) { acc[i][0] = bA.x; acc[i][1] = bA.y; acc[i][2] = bB.x; acc[i][3] = bB.y; }
    }
    for (int c = 0; c < 16; c++) {
        cp_wait<0>(); __syncthreads();
        if (c < 15) { stage_half(wb + ((c + 1) & 1) * 2048, W1 + (c + 1) * 2048, tid); cp_commit(); }
        const float* wv = wb + (c & 1) * 2048; int kb = c * 16;
#pragma unroll
        for (int k4 = 0; k4 < 16; k4 += 4) {
            float4 av[8];
#pragma unroll
            for (int i = 0; i < 8; i++) av[i] = *(const float4*)&s_in[(e0 + i) * 256 + kb + k4];
#pragma unroll
            for (int kk = 0; kk < 4; kk++) {
                const float* wr = wv + (k4 + kk) * 128 + c0;
                ulonglong2 w0 = *(const ulonglong2*)(wr), w1 = *(const ulonglong2*)(wr + 4);
#pragma unroll
                for (int i = 0; i < 8; i++) {
                    float a = (kk == 0) ? av[i].x : (kk == 1) ? av[i].y : (kk == 2) ? av[i].z : av[i].w;
                    ull adp = dup2(a);
                    acc[i][0] = fma2(adp, w0.x, acc[i][0]); acc[i][1] = fma2(adp, w0.y, acc[i][1]);
                    acc[i][2] = fma2(adp, w1.x, acc[i][2]); acc[i][3] = fma2(adp, w1.y, acc[i][3]);
                }
            }
        }
    }
    __syncthreads();
    stage_half(wb, W2, tid); cp_commit();
#pragma unroll
    for (int i = 0; i < 8; i++) {
        float2 p0 = unpack2(acc[i][0]), p1 = unpack2(acc[i][1]);
        float2 p2 = unpack2(acc[i][2]), p3 = unpack2(acc[i][3]);
        *(float4*)&s_hid[(e0 + i) * 128 + c0] =
            make_float4(fmaxf(p0.x, 0.f), fmaxf(p0.y, 0.f), fmaxf(p1.x, 0.f), fmaxf(p1.y, 0.f));
        *(float4*)&s_hid[(e0 + i) * 128 + c0 + 4] =
            make_float4(fmaxf(p2.x, 0.f), fmaxf(p2.y, 0.f), fmaxf(p3.x, 0.f), fmaxf(p3.y, 0.f));
    }
    ull acc2[8][4];
    {
        ulonglong2 bA = *(const ulonglong2*)(b2 + c0), bB = *(const ulonglong2*)(b2 + c0 + 4);
#pragma unroll
        for (int i = 0; i < 8; i++) { acc2[i][0] = bA.x; acc2[i][1] = bA.y; acc2[i][2] = bB.x; acc2[i][3] = bB.y; }
    }
    for (int c = 0; c < 8; c++) {
        cp_wait<0>(); __syncthreads();
        if (c < 7) { stage_half(wb + ((c + 1) & 1) * 2048, W2 + (c + 1) * 2048, tid); cp_commit(); }
        const float* wv = wb + (c & 1) * 2048; int kb = c * 16;
#pragma unroll
        for (int k4 = 0; k4 < 16; k4 += 4) {
            float4 av[8];
#pragma unroll
            for (int i = 0; i < 8; i++) av[i] = *(const float4*)&s_hid[(e0 + i) * 128 + kb + k4];
#pragma unroll
            for (int kk = 0; kk < 4; kk++) {
                const float* wr = wv + (k4 + kk) * 128 + c0;
                ulonglong2 w0 = *(const ulonglong2*)(wr), w1 = *(const ulonglong2*)(wr + 4);
#pragma unroll
                for (int i = 0; i < 8; i++) {
                    float a = (kk == 0) ? av[i].x : (kk == 1) ? av[i].y : (kk == 2) ? av[i].z : av[i].w;
                    ull adp = dup2(a);
                    acc2[i][0] = fma2(adp, w0.x, acc2[i][0]); acc2[i][1] = fma2(adp, w0.y, acc2[i][1]);
                    acc2[i][2] = fma2(adp, w1.x, acc2[i][2]); acc2[i][3] = fma2(adp, w1.y, acc2[i][3]);
                }
            }
        }
    }
    float4 g0 = *(const float4*)&gw[c0], g1 = *(const float4*)&gw[c0 + 4];
    float4 bb0 = *(const float4*)&gb[c0], bb1 = *(const float4*)&gb[c0 + 4];
#pragma unroll
    for (int i = 0; i < 8; i++) {
        int n = nb + e0 + i;
        float2 p0 = unpack2(acc2[i][0]), p1 = unpack2(acc2[i][1]);
        float2 p2 = unpack2(acc2[i][2]), p3 = unpack2(acc2[i][3]);
        float4 h0 = make_float4(0.f, 0.f, 0.f, 0.f), h1 = h0;
        if (n < NND) { h0 = *(const float4*)&g_h[n * HIDN + c0]; h1 = *(const float4*)&g_h[n * HIDN + c0 + 4]; }
        float o[8];
        o[0] = p0.x + h0.x; o[1] = p0.y + h0.y; o[2] = p1.x + h0.z; o[3] = p1.y + h0.w;
        o[4] = p2.x + h1.x; o[5] = p2.y + h1.y; o[6] = p3.x + h1.z; o[7] = p3.y + h1.w;
        float s = 0.f, q = 0.f;
#pragma unroll
        for (int k = 0; k < 8; k++) { s += o[k]; q += o[k] * o[k]; }
#pragma unroll
        for (int off = 1; off < 16; off <<= 1) {
            s += __shfl_xor_sync(0xffffffffu, s, off);
            q += __shfl_xor_sync(0xffffffffu, q, off);
        }
        float mean = s * (1.f / 128.f), var = q * (1.f / 128.f) - mean * mean;
        float rs = rsqrtf(var + 1e-5f);
        if (n < NND) {
            float4 r0, r1;
            r0.x = (o[0] - mean) * rs * g0.x + bb0.x; r0.y = (o[1] - mean) * rs * g0.y + bb0.y;
            r0.z = (o[2] - mean) * rs * g0.z + bb0.z; r0.w = (o[3] - mean) * rs * g0.w + bb0.w;
            r1.x = (o[4] - mean) * rs * g1.x + bb1.x; r1.y = (o[5] - mean) * rs * g1.y + bb1.y;
            r1.z = (o[6] - mean) * rs * g1.z + bb1.z; r1.w = (o[7] - mean) * rs * g1.w + bb1.w;
            *(float4*)&g_h[n * HIDN + c0] = r0;
            *(float4*)&g_h[n * HIDN + c0 + 4] = r1;
            *(float4*)&g_aggr[n * HIDN + c0] = make_float4(0.f, 0.f, 0.f, 0.f);
            *(float4*)&g_aggr[n * HIDN + c0 + 4] = make_float4(0.f, 0.f, 0.f, 0.f);
        }
    }
}
// ---------- encoder / head ----------
__device__ __forceinline__ void ln_store(float (*s_out)[HPAD], int nb, const float* gw, const float* gb) {
    int tid = threadIdx.x, nn = tid >> 3, p = tid & 7, n = nb + nn;
    float vals[16], sum = 0.f, sq = 0.f;
#pragma unroll
    for (int i = 0; i < 4; i++) {
        float4 t4 = *(float4*)&s_out[nn][16 * p + 4 * i];
        vals[4*i+0] = t4.x; vals[4*i+1] = t4.y; vals[4*i+2] = t4.z; vals[4*i+3] = t4.w;
        sum += t4.x + t4.y + t4.z + t4.w;
        sq += t4.x*t4.x + t4.y*t4.y + t4.z*t4.z + t4.w*t4.w;
    }
#pragma unroll
    for (int off = 4; off; off >>= 1) {
        sum += __shfl_xor_sync(0xffffffffu, sum, off);
        sq  += __shfl_xor_sync(0xffffffffu, sq, off);
    }
    float mean = sum * (1.f / 128.f), var = sq * (1.f / 128.f) - mean * mean;
    float rs = rsqrtf(var + 1e-5f);
    if (n < NND) {
#pragma unroll
        for (int i = 0; i < 4; i++) {
            int c = 16 * p + 4 * i; float4 o;
            o.x = (vals[4*i+0] - mean) * rs * gw[c+0] + gb[c+0];
            o.y = (vals[4*i+1] - mean) * rs * gw[c+1] + gb[c+1];
            o.z = (vals[4*i+2] - mean) * rs * gw[c+2] + gb[c+2];
            o.w = (vals[4*i+3] - mean) * rs * gw[c+3] + gb[c+3];
            *(float4*)&g_h[n * HIDN + c] = o;
        }
    }
}
__global__ __launch_bounds__(256) void encoder_kernel(const float* x, const float* W,
        const float* b, const float* gw, const float* gb) {
    __shared__ float s_in[TN][XPAD];
    __shared__ float s_out[TN][HPAD];
    int tid = threadIdx.x, lane = tid & 31, w = tid >> 5;
    int nb = blockIdx.x * TN;
    for (int j = w; j < TN; j += 8) {
        int n = nb + j;
        if (lane < 8) {
            float4 v = make_float4(0.f, 0.f, 0.f, 0.f);
            if (n < NND) v = *(const float4*)&x[n * NODE_IN + 4 * lane];
            *(float4*)&s_in[j][4 * lane] = v;
        }
    }
    __syncthreads();
    int cg = tid & 31, c0 = 4 * cg, eg = tid >> 5, e0 = 4 * eg;
    ull acc[4][2];
    {
        ull b01 = *(const ull*)(b + c0), b23 = *(const ull*)(b + c0 + 2);
#pragma unroll
        for (int i = 0; i < 4; i++) { acc[i][0] = b01; acc[i][1] = b23; }
    }
#pragma unroll
    for (int k = 0; k < NODE_IN; k++) {
        ulonglong2 wv = *(const ulonglong2*)(W + k * HIDN + c0);
#pragma unroll
        for (int i = 0; i < 4; i++) {
            ull a = dup2(s_in[e0 + i][k]);
            acc[i][0] = fma2(a, wv.x, acc[i][0]); acc[i][1] = fma2(a, wv.y, acc[i][1]);
        }
    }
#pragma unroll
    for (int i = 0; i < 4; i++) {
        float2 v0 = unpack2(acc[i][0]), v1 = unpack2(acc[i][1]);
        s_out[e0 + i][c0 + 0] = fmaxf(v0.x, 0.f); s_out[e0 + i][c0 + 1] = fmaxf(v0.y, 0.f);
        s_out[e0 + i][c0 + 2] = fmaxf(v1.x, 0.f); s_out[e0 + i][c0 + 3] = fmaxf(v1.y, 0.f);
    }
    __syncthreads();
    ln_store(s_out, nb, gw, gb);
}
__global__ __launch_bounds__(256) void head_kernel(const float* W, const float* b, float* out) {
    __shared__ float s_in[TN][HPAD];
    int tid = threadIdx.x, lane = tid & 31, w = tid >> 5;
    int nb = blockIdx.x * TN;
    for (int j = w; j < TN; j += 8) {
        int n = nb + j;
        float4 v = make_float4(0.f, 0.f, 0.f, 0.f);
        if (n < NND) v = *(const float4*)&g_h[n * HIDN + 4 * lane];
        *(float4*)&s_in[j][4 * lane] = v;
    }
    __syncthreads();
    int cg = tid & 31, c0 = 4 * cg, eg = tid >> 5, e0 = 4 * eg;
    ull acc[4][2];
    {
        ull b01 = *(const ull*)(b + c0), b23 = *(const ull*)(b + c0 + 2);
#pragma unroll
        for (int i = 0; i < 4; i++) { acc[i][0] = b01; acc[i][1] = b23; }
    }
#pragma unroll 4
    for (int k = 0; k < HIDN; k++) {
        ulonglong2 wv = *(const ulonglong2*)(W + k * HIDN + c0);
#pragma unroll
        for (int i = 0; i < 4; i++) {
            ull a = dup2(s_in[e0 + i][k]);
            acc[i][0] = fma2(a, wv.x, acc[i][0]); acc[i][1] = fma2(a, wv.y, acc[i][1]);
        }
    }
#pragma unroll
    for (int i = 0; i < 4; i++) {
        int n = nb + e0 + i;
        if (n < NND) {
            float2 v0 = unpack2(acc[i][0]), v1 = unpack2(acc[i][1]);
            *(float2*)&out[n * HIDN + c0 + 0] = v0;
            *(float2*)&out[n * HIDN + c0 + 2] = v1;
        }
    }
}
// ---------- launch ----------
extern "C" void kernel_launch(void* const* d_in, const int* in_sizes, int n_in,
                              void* d_out, int out_size) {
    const float* x      = (const float*)d_in[0];
    const void*  ei     = d_in[1];
    const float* ea     = (const float*)d_in[2];
    const float* enc_W  = (const float*)d_in[3];
    const float* enc_b  = (const float*)d_in[4];
    const float* enc_g  = (const float*)d_in[5];
    const float* enc_be = (const float*)d_in[6];
    const float* msg_W1 = (const float*)d_in[7];
    const float* msg_b1 = (const float*)d_in[8];
    const float* msg_W2 = (const float*)d_in[9];
    const float* msg_b2 = (const float*)d_in[10];
    const float* upd_W1 = (const float*)d_in[11];
    const float* upd_b1 = (const float*)d_in[12];
    const float* upd_W2 = (const float*)d_in[13];
    const float* upd_b2 = (const float*)d_in[14];
    const float* ln_g   = (const float*)d_in[15];
    const float* ln_be  = (const float*)d_in[16];
    const float* head_W = (const float*)d_in[17];
    const float* head_b = (const float*)d_in[18];
    float* out = (float*)d_out;

    cudaFuncSetAttribute(edge_mma, cudaFuncAttributeMaxDynamicSharedMemorySize, EK_SMEM);
    cudaFuncSetAttribute(update_kernel2, cudaFuncAttributeMaxDynamicSharedMemorySize, UPD_SMEM);

    init_kernel<<<256, 256>>>();
    detect_kernel<<<256, 256>>>((const unsigned*)ei);
    count_kernel<<<512, 256>>>(ei);
    inv_kernel<<<(NND + 255) / 256, 256>>>();
    pack_w1f<<<(2 * K8_1P * 512 + 255) / 256, 256>>>(msg_W1);
    pack_w2f<<<(2 * K8_2 * 512 + 255) / 256, 256>>>(msg_W2);

    int nblk32 = (NND + TN - 1) / TN, nblk64 = (NND + 63) / 64;
    encoder_kernel<<<nblk32, 256>>>(x, enc_W, enc_b, enc_g, enc_be);
    for (int l = 0; l < 2; l++) {
        edge_mma<<<NE / 64, 256, EK_SMEM>>>(ei, ea, msg_b1 + l * HIDN, msg_b2 + l * HIDN, l);
        update_kernel2<<<nblk64, 128, UPD_SMEM>>>(upd_W1 + l * UIN * HIDN, upd_b1 + l * HIDN,
                upd_W2 + l * HIDN * HIDN, upd_b2 + l * HIDN, ln_g + l * HIDN, ln_be + l * HIDN);
    }
    head_kernel<<<nblk32, 256>>>(head_W, head_b, out);
}